// round 13
// baseline (speedup 1.0000x reference)
#include <cuda_runtime.h>
#include <cuda_bf16.h>
#include <math.h>
#include <stdint.h>

// Problem constants
#define NN   12000      // nodes
#define NE   120000     // edges
#define FF   768        // feature width
#define PLD  4608       // node-projection row width (6 heads x 768)
#define SLOT ((size_t)FF * FF)   // elems per weight slot [768][768]

// ---------------- scratch (device globals; no allocation allowed) ------------
__device__ __nv_bfloat16 g_e1[(size_t)NE * FF];     // edge features, SORTED space
__device__ __nv_bfloat16 g_e2[(size_t)NE * FF];     // edge features (conv2 input)
__device__ __nv_bfloat16 g_Sf[(size_t)NE * FF];     // sigmoid(f-head) staging (conv1)
__device__ __nv_bfloat16 g_P [(size_t)NN * PLD];    // node projections (6 heads)
__device__ float         g_x [(size_t)NN * FF];     // running node features (fp32)
__device__ __nv_bfloat16 g_xb[(size_t)NN * FF];     // bf16 copy of node features
__device__ __nv_bfloat16 g_erb[(size_t)NE * 64];    // bf16 e_raw (original order)
__device__ __nv_bfloat16 g_Wt[(size_t)16 * SLOT];   // bf16 weight slots [K][768]
__device__ float         g_pool[FF];                // sum over nodes of x1
__device__ float         g_poolE[FF];               // sum over edges of msg2
// edge sort-by-dst machinery
__device__ int g_cnt [NN];      // histogram -> cursor
__device__ int g_perm[NE];      // sorted pos -> original edge id
__device__ int g_dstS[NE];      // dst in sorted order
__device__ int g_srcS[NE];      // src in sorted order

// ---------------- PTX helpers ------------------------------------------------
__device__ __forceinline__ uint32_t s2u(const void* p) {
    return (uint32_t)__cvta_generic_to_shared(p);
}
#define CPA16(dst, src, v) \
    asm volatile("cp.async.cg.shared.global [%0], [%1], 16, %2;" \
                 :: "r"(dst), "l"(src), "r"((v) ? 16 : 0))
#define CPA_COMMIT() asm volatile("cp.async.commit_group;" ::: "memory")
#define CPA_WAIT2()  asm volatile("cp.async.wait_group 2;" ::: "memory")
#define CPA_WAIT1()  asm volatile("cp.async.wait_group 1;" ::: "memory")
#define CPA_WAIT0()  asm volatile("cp.async.wait_group 0;" ::: "memory")

__device__ __forceinline__ void ldsm4(uint32_t* r, uint32_t addr) {
    asm volatile("ldmatrix.sync.aligned.m8n8.x4.shared.b16 {%0,%1,%2,%3},[%4];"
                 : "=r"(r[0]), "=r"(r[1]), "=r"(r[2]), "=r"(r[3]) : "r"(addr));
}
__device__ __forceinline__ void ldsm4t(uint32_t* r, uint32_t addr) {
    asm volatile("ldmatrix.sync.aligned.m8n8.x4.trans.shared.b16 {%0,%1,%2,%3},[%4];"
                 : "=r"(r[0]), "=r"(r[1]), "=r"(r[2]), "=r"(r[3]) : "r"(addr));
}
__device__ __forceinline__ void mma16816(float* c, const uint32_t* a, uint32_t b0, uint32_t b1) {
    asm volatile(
        "mma.sync.aligned.m16n8k16.row.col.f32.bf16.bf16.f32 "
        "{%0,%1,%2,%3},{%4,%5,%6,%7},{%8,%9},{%0,%1,%2,%3};"
        : "+f"(c[0]), "+f"(c[1]), "+f"(c[2]), "+f"(c[3])
        : "r"(a[0]), "r"(a[1]), "r"(a[2]), "r"(a[3]), "r"(b0), "r"(b1));
}
__device__ __forceinline__ uint32_t pk2(float a, float b) {
    __nv_bfloat162 h = __floats2bfloat162_rn(a, b);
    return *(uint32_t*)&h;
}
__device__ __forceinline__ void ub4(const __nv_bfloat16* p, float* o) {
    uint2 u = *(const uint2*)p;
    __nv_bfloat162 a = *(__nv_bfloat162*)&u.x;
    __nv_bfloat162 b = *(__nv_bfloat162*)&u.y;
    o[0] = __bfloat162float(a.x); o[1] = __bfloat162float(a.y);
    o[2] = __bfloat162float(b.x); o[3] = __bfloat162float(b.y);
}
__device__ __forceinline__ float sigm(float t) { return 1.f / (1.f + __expf(-t)); }

// ---------------- fused pipelined mma.sync GEMM (champion mainloop) -----------
// K-stage 32. smem: A 128x32 (stride 80B), B 32x128 (stride 272B), 4 buffers,
// prefetch distance 3, single __syncthreads per stage, 2 CTAs/SM.
// EPI_MSGFP (conv2): B tile interleaves Wf2/Ws2 at 16-col granularity; each
// thread owns matching f/s accumulators for the same feature cols, computes
// msg = relu(s)*sigmoid(f) in registers, and reduces into the 768-float pool
// (no Sf staging, no per-node scatter — x2 is only ever pool-summed).
enum { EPI_STORE = 0, EPI_TANH = 1, EPI_MSGS = 2, EPI_SG = 3, EPI_MSGFP = 4 };

#define A_TB  10240                    // 128*40*2
#define B_TB  8704                     // 32*136*2
#define SMEM_BYTES (4 * (A_TB + B_TB)) // 75776

struct GArgs {
    const __nv_bfloat16* A;    int lda; int M; int K;
    const __nv_bfloat16* B;    const __nv_bfloat16* B2; int ldb;   // [K][768]
    const float*         bias; const float* bias2;
    const __nv_bfloat16* Pd;   const __nv_bfloat16* Ps;   // primary head (ld PLD)
    const __nv_bfloat16* Pd2;  const __nv_bfloat16* Ps2;  // secondary head
    const int*           dst;  const int* srcI;
    const __nv_bfloat16* aux;  // MSGS: Sf, SG-gate: e_in (ld 768)
    __nv_bfloat16*       outb; __nv_bfloat16* outb2; int ldo;
    float*               atom; // MSGS: node accumulator (ld 768); MSGFP: g_poolE
    const int*           permA;    // TANH: gather A rows through this perm
    int                  multi;    // node-pass: slots merged into grid.x
    int                  slotBase;
};

template<int EPI>
__global__ void __launch_bounds__(256, 2) gemm_k(GArgs g) {
    extern __shared__ char smem_raw[];
    const uint32_t sb = s2u(smem_raw);

    const int tid = threadIdx.x, lane = tid & 31, warp = tid >> 5;
    const int bm = blockIdx.y * 128;

    // decode N-block / weight slot / pass variant
    int bn, outCol;
    bool isGate = false;
    const __nv_bfloat16* Bp = g.B;
    if (EPI == EPI_STORE && g.multi) {
        int idx = blockIdx.x / 6, nb = blockIdx.x % 6;
        int slot = g.slotBase + (idx >> 1) * 3 + (idx & 1);
        Bp += (size_t)slot * SLOT;
        bn = nb * 128;
        outCol = idx * 768 + nb * 128;
    } else if (EPI == EPI_SG) {
        isGate = blockIdx.x >= 6;
        if (isGate) Bp = g.B2;
        bn = (blockIdx.x % 6) * 128;
        outCol = bn;
    } else if (EPI == EPI_MSGFP) {
        bn = blockIdx.x * 64;          // 64 feature cols, f+s heads interleaved
        outCol = bn;
    } else {
        bn = blockIdx.x * 128;
        outCol = bn;
    }

    // ---- loader mapping: 1024 chunks of 16B (A 512 + B 512) per stage -------
    const int ar0 = tid >> 2, akc = tid & 3;
    const int br0 = tid >> 4, bkc = tid & 15;
    const uint32_t adst0 = ar0 * 80 + akc * 16;
    const uint32_t adst1 = adst0 + 64 * 80;
    const uint32_t bdst0 = br0 * 272 + bkc * 16;
    const uint32_t bdst1 = bdst0 + 16 * 272;
    const bool av0 = (bm + ar0) < g.M;
    const bool av1 = (bm + ar0 + 64) < g.M;
    int arow0 = min(bm + ar0,      g.M - 1);
    int arow1 = min(bm + ar0 + 64, g.M - 1);
    if (EPI == EPI_TANH && g.permA) { arow0 = g.permA[arow0]; arow1 = g.permA[arow1]; }
    const __nv_bfloat16* asrc0 = g.A + (size_t)arow0 * g.lda + akc * 8;
    const __nv_bfloat16* asrc1 = g.A + (size_t)arow1 * g.lda + akc * 8;
    // B source: MSGFP interleaves 16-col groups: even group->Wf2, odd->Ws2
    const __nv_bfloat16* bbase;
    int bcol;
    if (EPI == EPI_MSGFP) {
        bbase = ((bkc >> 1) & 1) ? g.B2 : g.B;
        bcol  = bn + ((bkc >> 2) << 4) + ((bkc & 1) << 3);
    } else {
        bbase = Bp;
        bcol  = bn + bkc * 8;
    }
    const __nv_bfloat16* bsrc0 = bbase + (size_t)br0        * g.ldb + bcol;
    const __nv_bfloat16* bsrc1 = bbase + (size_t)(br0 + 16) * g.ldb + bcol;
    const size_t bstep = (size_t)32 * g.ldb;

    auto load_stage = [&](int buf) {
        const uint32_t Ab = sb + buf * A_TB;
        const uint32_t Bb = sb + 4 * A_TB + buf * B_TB;
        CPA16(Ab + adst0, asrc0, av0);
        CPA16(Ab + adst1, asrc1, av1);
        CPA16(Bb + bdst0, bsrc0, true);
        CPA16(Bb + bdst1, bsrc1, true);
        asrc0 += 32; asrc1 += 32; bsrc0 += bstep; bsrc1 += bstep;
        CPA_COMMIT();
    };

    const int S = g.K >> 5;
    const int wm = (warp & 1) * 64;
    const int wn = (warp >> 1) * 32;

    float acc[4][4][4];
    #pragma unroll
    for (int i = 0; i < 4; i++)
        #pragma unroll
        for (int j = 0; j < 4; j++)
            #pragma unroll
            for (int k = 0; k < 4; k++) acc[i][j][k] = 0.f;

    const int pre = S < 3 ? S : 3;
    for (int p = 0; p < pre; p++) load_stage(p);

    for (int s = 0; s < S; s++) {
        const int rem = S - s - 1;
        if (rem >= 2)      CPA_WAIT2();
        else if (rem == 1) CPA_WAIT1();
        else               CPA_WAIT0();
        __syncthreads();
        if (s + 3 < S) load_stage((s + 3) & 3);

        const uint32_t Ab = sb + (s & 3) * A_TB;
        const uint32_t Bb = sb + 4 * A_TB + (s & 3) * B_TB;
        #pragma unroll
        for (int ks = 0; ks < 2; ks++) {
            uint32_t a[4][4], b[2][4];
            #pragma unroll
            for (int mi = 0; mi < 4; mi++)
                ldsm4(a[mi], Ab + ((wm + mi * 16 + (lane & 15)) * 40 + ks * 16 + (lane >> 4) * 8) * 2);
            #pragma unroll
            for (int np = 0; np < 2; np++)
                ldsm4t(b[np], Bb + ((ks * 16 + (lane & 15)) * 136 + wn + np * 16 + (lane >> 4) * 8) * 2);
            #pragma unroll
            for (int mi = 0; mi < 4; mi++)
                #pragma unroll
                for (int ni = 0; ni < 4; ni++)
                    mma16816(acc[mi][ni], a[mi], b[ni >> 1][(ni & 1) * 2], b[ni >> 1][(ni & 1) * 2 + 1]);
        }
    }

    // ------------------------------ epilogue ------------------------------
    const int tig = lane & 3;
    const int gid = lane >> 2;

    if (EPI == EPI_STORE || EPI == EPI_TANH) {
        #pragma unroll
        for (int mi = 0; mi < 4; mi++) {
            #pragma unroll
            for (int h = 0; h < 2; h++) {
                const int rr = bm + wm + mi * 16 + gid + h * 8;
                if (rr >= g.M) continue;
                #pragma unroll
                for (int ni = 0; ni < 4; ni++) {
                    const int cl = wn + ni * 8 + tig * 2;
                    const float v0 = acc[mi][ni][h * 2];
                    const float v1 = acc[mi][ni][h * 2 + 1];
                    if (EPI == EPI_STORE) {
                        *(uint32_t*)(g.outb + (size_t)rr * g.ldo + outCol + cl) = pk2(v0, v1);
                    } else {
                        const int c = bn + cl;
                        float2 bs = *(const float2*)(g.bias + c);
                        *(uint32_t*)(g.outb + (size_t)rr * g.ldo + c) =
                            pk2(tanhf(v0 + bs.x), tanhf(v1 + bs.y));
                    }
                }
            }
        }
        return;
    }

    const bool hi    = lane & 1;
    const int  pbase = (tig & 2) * 2;

    if (EPI == EPI_MSGFP) {
        // fused f/s epilogue with pool reduction: ni=np -> f-head, ni=np+2 ->
        // s-head, same feature cols featW+np*8+pbase.
        const int featW = bn + ((wn >> 5) << 4);
        float colacc[2][4];
        #pragma unroll
        for (int np = 0; np < 2; np++)
            #pragma unroll
            for (int k = 0; k < 4; k++) colacc[np][k] = 0.f;

        #pragma unroll
        for (int mi = 0; mi < 4; mi++) {
            const int rr = bm + wm + mi * 16 + gid + (hi ? 8 : 0);
            const bool val = rr < g.M;
            int di = 0, si = 0;
            if (val) { di = g.dst[rr]; si = g.srcI[rr]; }
            float vv[4][4];
            #pragma unroll
            for (int ni = 0; ni < 4; ni++) {
                const float x0 = acc[mi][ni][0], x1 = acc[mi][ni][1];
                const float x2 = acc[mi][ni][2], x3 = acc[mi][ni][3];
                const float r0 = __shfl_xor_sync(0xffffffffu, x0, 1);
                const float r1 = __shfl_xor_sync(0xffffffffu, x1, 1);
                const float r2 = __shfl_xor_sync(0xffffffffu, x2, 1);
                const float r3 = __shfl_xor_sync(0xffffffffu, x3, 1);
                if (!hi) { vv[ni][0] = x0; vv[ni][1] = x1; vv[ni][2] = r0; vv[ni][3] = r1; }
                else     { vv[ni][0] = r2; vv[ni][1] = r3; vv[ni][2] = x2; vv[ni][3] = x3; }
            }
            if (!val) continue;
            #pragma unroll
            for (int np = 0; np < 2; np++) {
                const int c = featW + np * 8 + pbase;
                float pdf[4], psf[4], pds[4], pss[4];
                ub4(g.Pd  + (size_t)di * PLD + c, pdf);
                ub4(g.Ps  + (size_t)si * PLD + c, psf);
                ub4(g.Pd2 + (size_t)di * PLD + c, pds);
                ub4(g.Ps2 + (size_t)si * PLD + c, pss);
                float4 bf4 = *(const float4*)(g.bias  + c);
                float4 bs4 = *(const float4*)(g.bias2 + c);
                const float* fb = &bf4.x;
                const float* sb2 = &bs4.x;
                #pragma unroll
                for (int k = 0; k < 4; k++) {
                    float fv = vv[np][k]     + pdf[k] + psf[k] + fb[k];
                    float sv = vv[np + 2][k] + pds[k] + pss[k] + sb2[k];
                    colacc[np][k] += fmaxf(sv, 0.f) * sigm(fv);
                }
            }
        }
        // reduce across rows (gid strides 16/8/4, then hi pairs), atomically add
        #pragma unroll
        for (int np = 0; np < 2; np++) {
            #pragma unroll
            for (int k = 0; k < 4; k++) {
                float v = colacc[np][k];
                float o;
                o = __shfl_down_sync(0xffffffffu, v, 16); if (lane < 16) v += o;
                o = __shfl_down_sync(0xffffffffu, v, 8);  if (lane < 8)  v += o;
                o = __shfl_down_sync(0xffffffffu, v, 4);  if (lane < 4)  v += o;
                o = __shfl_down_sync(0xffffffffu, v, 1);  if ((lane & 1) == 0) v += o;
                colacc[np][k] = v;
            }
        }
        if (lane == 0 || lane == 2) {
            const int pb = (lane == 0) ? 0 : 4;
            #pragma unroll
            for (int np = 0; np < 2; np++) {
                const int c = featW + np * 8 + pb;
                atomicAdd((float4*)(g.atom + c),
                          make_float4(colacc[np][0], colacc[np][1], colacc[np][2], colacc[np][3]));
            }
        }
        return;
    }

    // ---- pair-exchange epilogue (SG / MSGS): lanes t,t^1 swap halves so each
    // lane owns 4 consecutive cols of one row (even->h0, odd->h1).
    const float*         bias = g.bias;
    const __nv_bfloat16* Pd   = g.Pd;
    const __nv_bfloat16* Ps   = g.Ps;
    __nv_bfloat16*       outb = g.outb;
    if (EPI == EPI_SG && isGate) {
        bias = g.bias2; Pd = g.Pd2; Ps = g.Ps2; outb = g.outb2;
    }

    #pragma unroll
    for (int mi = 0; mi < 4; mi++) {
        const int rr = bm + wm + mi * 16 + gid + (hi ? 8 : 0);
        const bool val = rr < g.M;
        int di = 0, si = 0;
        if (val) { di = g.dst[rr]; si = g.srcI[rr]; }
        #pragma unroll
        for (int ni = 0; ni < 4; ni++) {
            const float x0 = acc[mi][ni][0], x1 = acc[mi][ni][1];
            const float x2 = acc[mi][ni][2], x3 = acc[mi][ni][3];
            const float r0 = __shfl_xor_sync(0xffffffffu, x0, 1);
            const float r1 = __shfl_xor_sync(0xffffffffu, x1, 1);
            const float r2 = __shfl_xor_sync(0xffffffffu, x2, 1);
            const float r3 = __shfl_xor_sync(0xffffffffu, x3, 1);
            float v[4];
            if (!hi) { v[0] = x0; v[1] = x1; v[2] = r0; v[3] = r1; }
            else     { v[0] = r2; v[1] = r3; v[2] = x2; v[3] = x3; }
            if (!val) continue;
            const int c = bn + wn + ni * 8 + pbase;
            float pd[4], ps[4], t[4];
            ub4(Pd + (size_t)di * PLD + c, pd);
            ub4(Ps + (size_t)si * PLD + c, ps);
            float4 bs = *(const float4*)(bias + c);
            t[0] = v[0] + pd[0] + ps[0] + bs.x;
            t[1] = v[1] + pd[1] + ps[1] + bs.y;
            t[2] = v[2] + pd[2] + ps[2] + bs.z;
            t[3] = v[3] + pd[3] + ps[3] + bs.w;
            if (EPI == EPI_SG) {
                if (isGate) {
                    float av[4];
                    ub4(g.aux + (size_t)rr * 768 + c, av);
                    uint2 o = make_uint2(pk2(av[0] * (1.f + sigm(t[0])), av[1] * (1.f + sigm(t[1]))),
                                         pk2(av[2] * (1.f + sigm(t[2])), av[3] * (1.f + sigm(t[3]))));
                    *(uint2*)(outb + (size_t)rr * 768 + c) = o;
                } else {
                    uint2 o = make_uint2(pk2(sigm(t[0]), sigm(t[1])), pk2(sigm(t[2]), sigm(t[3])));
                    *(uint2*)(outb + (size_t)rr * 768 + c) = o;
                }
            } else { // EPI_MSGS
                float av[4];
                ub4(g.aux + (size_t)rr * 768 + c, av);
                float4 m = make_float4(fmaxf(t[0], 0.f) * av[0], fmaxf(t[1], 0.f) * av[1],
                                       fmaxf(t[2], 0.f) * av[2], fmaxf(t[3], 0.f) * av[3]);
                atomicAdd((float4*)(g.atom + (size_t)di * 768 + c), m);
            }
        }
    }
}

// ---------------- edge sort kernels -------------------------------------------
__global__ void zero_cnt_kernel() {
    int i = blockIdx.x * blockDim.x + threadIdx.x;
    if (i < NN) g_cnt[i] = 0;
}
__global__ void hist_kernel(const int* __restrict__ dst) {
    int e = blockIdx.x * blockDim.x + threadIdx.x;
    if (e < NE) atomicAdd(&g_cnt[dst[e]], 1);
}
__global__ void scan_kernel() {   // 1 block, 1024 threads; 12 bins/thread
    __shared__ int sh[1024];
    const int t = threadIdx.x;
    const int base = t * 12;
    int loc[12];
    int sum = 0;
    #pragma unroll
    for (int i = 0; i < 12; i++) {
        int idx = base + i;
        int c = (idx < NN) ? g_cnt[idx] : 0;
        loc[i] = sum; sum += c;
    }
    sh[t] = sum;
    __syncthreads();
    for (int off = 1; off < 1024; off <<= 1) {
        int v = (t >= off) ? sh[t - off] : 0;
        __syncthreads();
        sh[t] += v;
        __syncthreads();
    }
    const int excl = (t == 0) ? 0 : sh[t - 1];
    #pragma unroll
    for (int i = 0; i < 12; i++) {
        int idx = base + i;
        if (idx < NN) g_cnt[idx] = excl + loc[i];   // cursor = exclusive base
    }
}
__global__ void scatter_kernel(const int* __restrict__ dst, const int* __restrict__ src) {
    int e = blockIdx.x * blockDim.x + threadIdx.x;
    if (e >= NE) return;
    int d = dst[e];
    int pos = atomicAdd(&g_cnt[d], 1);
    g_perm[pos] = e;
    g_dstS[pos] = d;
    g_srcS[pos] = src[e];
}

// ---------------- small kernels ----------------------------------------------
__global__ void cvt_x_kernel(const float* __restrict__ x) {
    int i = blockIdx.x * blockDim.x + threadIdx.x;
    const int n4 = NN * FF / 4;
    if (i < n4) {
        float4 v = ((const float4*)x)[i];
        ((float4*)g_x)[i] = v;
        ((__nv_bfloat162*)g_xb)[i * 2]     = __floats2bfloat162_rn(v.x, v.y);
        ((__nv_bfloat162*)g_xb)[i * 2 + 1] = __floats2bfloat162_rn(v.z, v.w);
    }
    if (i < FF) { g_pool[i] = 0.f; g_poolE[i] = 0.f; }
}
__global__ void cvt_bf16_kernel(const float* __restrict__ s, __nv_bfloat16* __restrict__ d, int n4) {
    int i = blockIdx.x * blockDim.x + threadIdx.x;
    if (i < n4) {
        float4 v = ((const float4*)s)[i];
        ((__nv_bfloat162*)d)[i * 2]     = __floats2bfloat162_rn(v.x, v.y);
        ((__nv_bfloat162*)d)[i * 2 + 1] = __floats2bfloat162_rn(v.z, v.w);
    }
}
__global__ void cvt_w_kernel(const float* Wf1, const float* Ws1, const float* We1,
                             const float* Wf2, const float* Ws2, const float* Wp) {
    int i = blockIdx.x * blockDim.x + threadIdx.x;    // float4 index
    const int big = (int)(3 * SLOT / 4);
    const float* s;
    __nv_bfloat16* d;
    if (i < 5 * big) {
        int w = i / big, r = i - w * big;
        const float* sv = Wf1;
        if (w == 1) sv = Ws1; else if (w == 2) sv = We1;
        else if (w == 3) sv = Wf2; else if (w == 4) sv = Ws2;
        s = sv + (size_t)r * 4;
        d = g_Wt + (size_t)w * 3 * SLOT + (size_t)r * 4;
    } else {
        int r = i - 5 * big;
        if (r >= 64 * FF / 4) return;
        s = Wp + (size_t)r * 4;
        d = g_Wt + (size_t)15 * SLOT + (size_t)r * 4;
    }
    float4 v = *(const float4*)s;
    *(__nv_bfloat162*)d       = __floats2bfloat162_rn(v.x, v.y);
    *(__nv_bfloat162*)(d + 2) = __floats2bfloat162_rn(v.z, v.w);
}
__global__ void pool_kernel() {
    int c  = blockIdx.x * blockDim.x + threadIdx.x;
    int r0 = blockIdx.y * 240;
    int r1 = min(r0 + 240, NN);
    float s = 0.f;
    for (int r = r0; r < r1; r++) s += g_x[(size_t)r * FF + c];
    atomicAdd(&g_pool[c], s);
}
__global__ void final_kernel(const float* __restrict__ Wd, const float* __restrict__ bd,
                             float* __restrict__ out) {
    int l = threadIdx.x;
    float logit = -1e30f;
    if (l < 16) {
        float s = bd[l];
        #pragma unroll 8
        for (int f = 0; f < FF; f++) s += (g_pool[f] + g_poolE[f]) * Wd[f * 16 + l];
        logit = s;
    }
    float m = logit;
    #pragma unroll
    for (int o = 16; o > 0; o >>= 1) m = fmaxf(m, __shfl_xor_sync(0xffffffffu, m, o));
    float e = (l < 16) ? __expf(logit - m) : 0.f;
    float sum = e;
    #pragma unroll
    for (int o = 16; o > 0; o >>= 1) sum += __shfl_xor_sync(0xffffffffu, sum, o);
    if (l < 16) out[l] = e / sum;
}

// ---------------- host orchestration ------------------------------------------
extern "C" void kernel_launch(void* const* d_in, const int* in_sizes, int n_in,
                              void* d_out, int out_size) {
    (void)in_sizes; (void)n_in; (void)out_size;
    const float* x     = (const float*)d_in[0];
    const float* e_raw = (const float*)d_in[1];
    const int*   src   = (const int*)d_in[2];
    const int*   dst   = (const int*)d_in[3];
    const float* W_pre = (const float*)d_in[4];
    const float* b_pre = (const float*)d_in[5];
    const float* Wf1 = (const float*)d_in[6],  *bf1 = (const float*)d_in[7];
    const float* Ws1 = (const float*)d_in[8],  *bs1 = (const float*)d_in[9];
    const float* We1 = (const float*)d_in[10], *be1 = (const float*)d_in[11];
    const float* Wf2 = (const float*)d_in[12], *bf2 = (const float*)d_in[13];
    const float* Ws2 = (const float*)d_in[14], *bs2 = (const float*)d_in[15];
    const float* Wd  = (const float*)d_in[18], *bd  = (const float*)d_in[19];

    void *pe1v, *pe2v, *pSfv, *pPv, *pxv, *pxbv, *perbv, *pWtv, *ppermv, *pdstSv, *psrcSv, *ppoolEv;
    cudaGetSymbolAddress(&pe1v,   g_e1);
    cudaGetSymbolAddress(&pe2v,   g_e2);
    cudaGetSymbolAddress(&pSfv,   g_Sf);
    cudaGetSymbolAddress(&pPv,    g_P);
    cudaGetSymbolAddress(&pxv,    g_x);
    cudaGetSymbolAddress(&pxbv,   g_xb);
    cudaGetSymbolAddress(&perbv,  g_erb);
    cudaGetSymbolAddress(&pWtv,   g_Wt);
    cudaGetSymbolAddress(&ppermv, g_perm);
    cudaGetSymbolAddress(&pdstSv, g_dstS);
    cudaGetSymbolAddress(&psrcSv, g_srcS);
    cudaGetSymbolAddress(&ppoolEv, g_poolE);
    __nv_bfloat16* pe1   = (__nv_bfloat16*)pe1v;
    __nv_bfloat16* pe2   = (__nv_bfloat16*)pe2v;
    __nv_bfloat16* pSf   = (__nv_bfloat16*)pSfv;
    __nv_bfloat16* pP    = (__nv_bfloat16*)pPv;
    float*         px    = (float*)pxv;
    __nv_bfloat16* pxb   = (__nv_bfloat16*)pxbv;
    __nv_bfloat16* perb  = (__nv_bfloat16*)perbv;
    __nv_bfloat16* pWt   = (__nv_bfloat16*)pWtv;
    const int*     pperm = (const int*)ppermv;
    const int*     pdstS = (const int*)pdstSv;
    const int*     psrcS = (const int*)psrcSv;
    float*         ppoolE = (float*)ppoolEv;

    cudaFuncSetAttribute(gemm_k<EPI_STORE>, cudaFuncAttributeMaxDynamicSharedMemorySize, SMEM_BYTES);
    cudaFuncSetAttribute(gemm_k<EPI_TANH>,  cudaFuncAttributeMaxDynamicSharedMemorySize, SMEM_BYTES);
    cudaFuncSetAttribute(gemm_k<EPI_MSGS>,  cudaFuncAttributeMaxDynamicSharedMemorySize, SMEM_BYTES);
    cudaFuncSetAttribute(gemm_k<EPI_SG>,    cudaFuncAttributeMaxDynamicSharedMemorySize, SMEM_BYTES);
    cudaFuncSetAttribute(gemm_k<EPI_MSGFP>, cudaFuncAttributeMaxDynamicSharedMemorySize, SMEM_BYTES);

    const dim3 blk(256);
    const dim3 gE(6,  (NE + 127) / 128);
    const dim3 gSG(12, (NE + 127) / 128);
    const dim3 gMF(12, (NE + 127) / 128);
    const dim3 gN1(36, (NN + 127) / 128);
    const dim3 gN2(24, (NN + 127) / 128);
    auto slot = [&](int i) { return pWt + (size_t)i * SLOT; };

    // (1) x -> g_x + g_xb   (2) e_raw -> bf16   (3) weights -> bf16
    cvt_x_kernel<<<(NN * FF / 4 + 255) / 256, blk>>>(x);
    cvt_bf16_kernel<<<(NE * 64 / 4 + 255) / 256, blk>>>(e_raw, perb, NE * 64 / 4);
    {
        const int tot4 = 5 * (int)(3 * SLOT / 4) + 64 * FF / 4;
        cvt_w_kernel<<<(tot4 + 255) / 256, blk>>>(Wf1, Ws1, We1, Wf2, Ws2, W_pre);
    }

    auto node_pass = [&](int slotBase, dim3 grid) {
        GArgs a = {};
        a.A = pxb; a.lda = 768; a.M = NN; a.K = 768;
        a.B = pWt; a.ldb = 768;
        a.outb = pP; a.ldo = PLD;
        a.multi = 1; a.slotBase = slotBase;
        gemm_k<EPI_STORE><<<grid, blk, SMEM_BYTES>>>(a);
    };

    // (4) conv1 node projections  [ncu capture target]
    node_pass(0, gN1);

    // (5-8) edge counting-sort by dst: hist -> scan -> scatter
    zero_cnt_kernel<<<(NN + 255) / 256, blk>>>();
    hist_kernel<<<(NE + 255) / 256, blk>>>(dst);
    scan_kernel<<<1, 1024>>>();
    scatter_kernel<<<(NE + 255) / 256, blk>>>(dst, src);

    // (9) pre-edge: e1[sorted] = tanh(e_raw[perm] @ W_pre + b_pre)
    {
        GArgs a = {};
        a.A = perb; a.lda = 64; a.M = NE; a.K = 64;
        a.B = slot(15); a.ldb = 768; a.bias = b_pre;
        a.outb = pe1; a.ldo = 768;
        a.permA = pperm;
        gemm_k<EPI_TANH><<<gE, blk, SMEM_BYTES>>>(a);
    }

    // (10) conv1 merged SIGF+GATE: Sf = sigmoid(f-head), e2 = e1*(1+sigmoid(e-head))
    {
        GArgs a = {};
        a.A = pe1; a.lda = 768; a.M = NE; a.K = 768;
        a.B = slot(2); a.B2 = slot(8); a.ldb = 768;
        a.bias = bf1; a.bias2 = be1;
        a.Pd = pP + 0;     a.Ps = pP + 768;    // f-head projections
        a.Pd2 = pP + 3072; a.Ps2 = pP + 3840;  // e-head projections
        a.dst = pdstS; a.srcI = psrcS;
        a.aux = pe1; a.outb = pSf; a.outb2 = pe2; a.ldo = 768;
        gemm_k<EPI_SG><<<gSG, blk, SMEM_BYTES>>>(a);
    }

    // (11) conv1 MSGS: x += scatter(relu(s-head) * Sf)   (x1 needed per-node)
    {
        GArgs a = {};
        a.A = pe1; a.lda = 768; a.M = NE; a.K = 768;
        a.B = slot(5); a.ldb = 768; a.bias = bs1;
        a.Pd = pP + 1536; a.Ps = pP + 2304;
        a.dst = pdstS; a.srcI = psrcS;
        a.aux = pSf; a.ldo = 768; a.atom = px;
        gemm_k<EPI_MSGS><<<gE, blk, SMEM_BYTES>>>(a);
    }

    // (12) refresh bf16 node features (x1)
    cvt_bf16_kernel<<<(NN * FF / 4 + 255) / 256, blk>>>(px, pxb, NN * FF / 4);

    // (13) conv2 node projections
    node_pass(9, gN2);

    // (14) conv2 fused f+s message pass with pool reduction:
    //      pool += sum_e relu(s-head)*sigmoid(f-head)   (no Sf staging, no scatter)
    {
        GArgs a = {};
        a.A = pe2; a.lda = 768; a.M = NE; a.K = 768;
        a.B = slot(11); a.B2 = slot(14); a.ldb = 768;
        a.bias = bf2; a.bias2 = bs2;
        a.Pd  = pP + 0;    a.Ps  = pP + 768;    // f-head projections
        a.Pd2 = pP + 1536; a.Ps2 = pP + 2304;   // s-head projections
        a.dst = pdstS; a.srcI = psrcS;
        a.atom = ppoolE;
        gemm_k<EPI_MSGFP><<<gMF, blk, SMEM_BYTES>>>(a);
    }

    // (15,16) pool(x1) + dense + softmax (adds g_poolE)
    pool_kernel<<<dim3(3, 50), blk>>>();
    final_kernel<<<1, 32>>>(Wd, bd, (float*)d_out);
}

// round 14
// speedup vs baseline: 1.0196x; 1.0196x over previous
#include <cuda_runtime.h>
#include <cuda_bf16.h>
#include <math.h>
#include <stdint.h>

// Problem constants
#define NN   12000      // nodes
#define NE   120000     // edges
#define FF   768        // feature width
#define PLD  4608       // node-projection row width (6 heads x 768)
#define SLOT ((size_t)FF * FF)   // elems per weight slot [768][768]

// ---------------- scratch (device globals; no allocation allowed) ------------
__device__ __nv_bfloat16 g_e1[(size_t)NE * FF];     // edge features, SORTED space
__device__ __nv_bfloat16 g_e2[(size_t)NE * FF];     // edge features (conv2 input)
__device__ __nv_bfloat16 g_Sf[(size_t)NE * FF];     // sigmoid(f-head) staging
__device__ __nv_bfloat16 g_P [(size_t)NN * PLD];    // node projections (6 heads)
__device__ float         g_x [(size_t)NN * FF];     // running node features (fp32)
__device__ __nv_bfloat16 g_xb[(size_t)NN * FF];     // bf16 copy of node features
__device__ __nv_bfloat16 g_erb[(size_t)NE * 64];    // bf16 e_raw (original order)
__device__ __nv_bfloat16 g_Wt[(size_t)16 * SLOT];   // bf16 weight slots [K][768]
__device__ float         g_pool[FF];                // sum over nodes of x1
__device__ float         g_poolE[FF];               // sum over edges of msg2
// edge sort-by-dst machinery
__device__ int g_cnt [NN];      // histogram -> cursor
__device__ int g_perm[NE];      // sorted pos -> original edge id
__device__ int g_dstS[NE];      // dst in sorted order
__device__ int g_srcS[NE];      // src in sorted order

// ---------------- PTX helpers ------------------------------------------------
__device__ __forceinline__ uint32_t s2u(const void* p) {
    return (uint32_t)__cvta_generic_to_shared(p);
}
#define CPA16(dst, src, v) \
    asm volatile("cp.async.cg.shared.global [%0], [%1], 16, %2;" \
                 :: "r"(dst), "l"(src), "r"((v) ? 16 : 0))
#define CPA_COMMIT() asm volatile("cp.async.commit_group;" ::: "memory")
#define CPA_WAIT2()  asm volatile("cp.async.wait_group 2;" ::: "memory")
#define CPA_WAIT1()  asm volatile("cp.async.wait_group 1;" ::: "memory")
#define CPA_WAIT0()  asm volatile("cp.async.wait_group 0;" ::: "memory")

__device__ __forceinline__ void ldsm4(uint32_t* r, uint32_t addr) {
    asm volatile("ldmatrix.sync.aligned.m8n8.x4.shared.b16 {%0,%1,%2,%3},[%4];"
                 : "=r"(r[0]), "=r"(r[1]), "=r"(r[2]), "=r"(r[3]) : "r"(addr));
}
__device__ __forceinline__ void ldsm4t(uint32_t* r, uint32_t addr) {
    asm volatile("ldmatrix.sync.aligned.m8n8.x4.trans.shared.b16 {%0,%1,%2,%3},[%4];"
                 : "=r"(r[0]), "=r"(r[1]), "=r"(r[2]), "=r"(r[3]) : "r"(addr));
}
__device__ __forceinline__ void mma16816(float* c, const uint32_t* a, uint32_t b0, uint32_t b1) {
    asm volatile(
        "mma.sync.aligned.m16n8k16.row.col.f32.bf16.bf16.f32 "
        "{%0,%1,%2,%3},{%4,%5,%6,%7},{%8,%9},{%0,%1,%2,%3};"
        : "+f"(c[0]), "+f"(c[1]), "+f"(c[2]), "+f"(c[3])
        : "r"(a[0]), "r"(a[1]), "r"(a[2]), "r"(a[3]), "r"(b0), "r"(b1));
}
__device__ __forceinline__ uint32_t pk2(float a, float b) {
    __nv_bfloat162 h = __floats2bfloat162_rn(a, b);
    return *(uint32_t*)&h;
}
__device__ __forceinline__ void ub4(const __nv_bfloat16* p, float* o) {
    uint2 u = *(const uint2*)p;
    __nv_bfloat162 a = *(__nv_bfloat162*)&u.x;
    __nv_bfloat162 b = *(__nv_bfloat162*)&u.y;
    o[0] = __bfloat162float(a.x); o[1] = __bfloat162float(a.y);
    o[2] = __bfloat162float(b.x); o[3] = __bfloat162float(b.y);
}
__device__ __forceinline__ float sigm(float t) { return 1.f / (1.f + __expf(-t)); }

// ---------------- fused pipelined mma.sync GEMM (champion mainloop) -----------
// K-stage 32. smem: A 128x32 (stride 80B), B 32x128 (stride 272B), 4 buffers,
// prefetch distance 3, single __syncthreads per stage, 2 CTAs/SM.
// EPI_MSGP: conv2 message pass; messages are only pool-summed (Σ over edges),
// never scattered per-node — per-warp reduce + few atomics into g_poolE.
enum { EPI_STORE = 0, EPI_TANH = 1, EPI_SIGF = 2, EPI_MSGS = 3, EPI_SG = 4, EPI_MSGP = 5 };

#define A_TB  10240                    // 128*40*2
#define B_TB  8704                     // 32*136*2
#define SMEM_BYTES (4 * (A_TB + B_TB)) // 75776

struct GArgs {
    const __nv_bfloat16* A;    int lda; int M; int K;
    const __nv_bfloat16* B;    const __nv_bfloat16* B2; int ldb;   // [K][768]
    const float*         bias; const float* bias2;
    const __nv_bfloat16* Pd;   const __nv_bfloat16* Ps;   // primary head (ld PLD)
    const __nv_bfloat16* Pd2;  const __nv_bfloat16* Ps2;  // secondary head (SG gate)
    const int*           dst;  const int* srcI;
    const __nv_bfloat16* aux;  // MSGS/MSGP: Sf, SG-gate: e_in (ld 768)
    __nv_bfloat16*       outb; __nv_bfloat16* outb2; int ldo;
    float*               atom; // MSGS: node accumulator (ld 768); MSGP: g_poolE
    const int*           permA;    // TANH: gather A rows through this perm
    int                  multi;    // node-pass: slots merged into grid.x
    int                  slotBase;
};

template<int EPI>
__global__ void __launch_bounds__(256, 2) gemm_k(GArgs g) {
    extern __shared__ char smem_raw[];
    const uint32_t sb = s2u(smem_raw);

    const int tid = threadIdx.x, lane = tid & 31, warp = tid >> 5;
    const int bm = blockIdx.y * 128;

    // decode N-block / weight slot / pass variant
    int bn, outCol;
    bool isGate = false;
    const __nv_bfloat16* Bp = g.B;
    if (EPI == EPI_STORE && g.multi) {
        int idx = blockIdx.x / 6, nb = blockIdx.x % 6;
        int slot = g.slotBase + (idx >> 1) * 3 + (idx & 1);
        Bp += (size_t)slot * SLOT;
        bn = nb * 128;
        outCol = idx * 768 + nb * 128;
    } else if (EPI == EPI_SG) {
        isGate = blockIdx.x >= 6;
        if (isGate) Bp = g.B2;
        bn = (blockIdx.x % 6) * 128;
        outCol = bn;
    } else {
        bn = blockIdx.x * 128;
        outCol = bn;
    }

    // ---- loader mapping: 1024 chunks of 16B (A 512 + B 512) per stage -------
    const int ar0 = tid >> 2, akc = tid & 3;
    const int br0 = tid >> 4, bkc = tid & 15;
    const uint32_t adst0 = ar0 * 80 + akc * 16;
    const uint32_t adst1 = adst0 + 64 * 80;
    const uint32_t bdst0 = br0 * 272 + bkc * 16;
    const uint32_t bdst1 = bdst0 + 16 * 272;
    const bool av0 = (bm + ar0) < g.M;
    const bool av1 = (bm + ar0 + 64) < g.M;
    int arow0 = min(bm + ar0,      g.M - 1);
    int arow1 = min(bm + ar0 + 64, g.M - 1);
    if (EPI == EPI_TANH && g.permA) { arow0 = g.permA[arow0]; arow1 = g.permA[arow1]; }
    const __nv_bfloat16* asrc0 = g.A + (size_t)arow0 * g.lda + akc * 8;
    const __nv_bfloat16* asrc1 = g.A + (size_t)arow1 * g.lda + akc * 8;
    const __nv_bfloat16* bsrc0 = Bp + (size_t)br0        * g.ldb + bn + bkc * 8;
    const __nv_bfloat16* bsrc1 = Bp + (size_t)(br0 + 16) * g.ldb + bn + bkc * 8;
    const size_t bstep = (size_t)32 * g.ldb;

    auto load_stage = [&](int buf) {
        const uint32_t Ab = sb + buf * A_TB;
        const uint32_t Bb = sb + 4 * A_TB + buf * B_TB;
        CPA16(Ab + adst0, asrc0, av0);
        CPA16(Ab + adst1, asrc1, av1);
        CPA16(Bb + bdst0, bsrc0, true);
        CPA16(Bb + bdst1, bsrc1, true);
        asrc0 += 32; asrc1 += 32; bsrc0 += bstep; bsrc1 += bstep;
        CPA_COMMIT();
    };

    const int S = g.K >> 5;
    const int wm = (warp & 1) * 64;
    const int wn = (warp >> 1) * 32;

    float acc[4][4][4];
    #pragma unroll
    for (int i = 0; i < 4; i++)
        #pragma unroll
        for (int j = 0; j < 4; j++)
            #pragma unroll
            for (int k = 0; k < 4; k++) acc[i][j][k] = 0.f;

    const int pre = S < 3 ? S : 3;
    for (int p = 0; p < pre; p++) load_stage(p);

    for (int s = 0; s < S; s++) {
        const int rem = S - s - 1;
        if (rem >= 2)      CPA_WAIT2();
        else if (rem == 1) CPA_WAIT1();
        else               CPA_WAIT0();
        __syncthreads();
        if (s + 3 < S) load_stage((s + 3) & 3);

        const uint32_t Ab = sb + (s & 3) * A_TB;
        const uint32_t Bb = sb + 4 * A_TB + (s & 3) * B_TB;
        #pragma unroll
        for (int ks = 0; ks < 2; ks++) {
            uint32_t a[4][4], b[2][4];
            #pragma unroll
            for (int mi = 0; mi < 4; mi++)
                ldsm4(a[mi], Ab + ((wm + mi * 16 + (lane & 15)) * 40 + ks * 16 + (lane >> 4) * 8) * 2);
            #pragma unroll
            for (int np = 0; np < 2; np++)
                ldsm4t(b[np], Bb + ((ks * 16 + (lane & 15)) * 136 + wn + np * 16 + (lane >> 4) * 8) * 2);
            #pragma unroll
            for (int mi = 0; mi < 4; mi++)
                #pragma unroll
                for (int ni = 0; ni < 4; ni++)
                    mma16816(acc[mi][ni], a[mi], b[ni >> 1][(ni & 1) * 2], b[ni >> 1][(ni & 1) * 2 + 1]);
        }
    }

    // ------------------------------ epilogue ------------------------------
    const int tig = lane & 3;
    const int gid = lane >> 2;

    if (EPI == EPI_STORE || EPI == EPI_TANH) {
        #pragma unroll
        for (int mi = 0; mi < 4; mi++) {
            #pragma unroll
            for (int h = 0; h < 2; h++) {
                const int rr = bm + wm + mi * 16 + gid + h * 8;
                if (rr >= g.M) continue;
                #pragma unroll
                for (int ni = 0; ni < 4; ni++) {
                    const int cl = wn + ni * 8 + tig * 2;
                    const float v0 = acc[mi][ni][h * 2];
                    const float v1 = acc[mi][ni][h * 2 + 1];
                    if (EPI == EPI_STORE) {
                        *(uint32_t*)(g.outb + (size_t)rr * g.ldo + outCol + cl) = pk2(v0, v1);
                    } else {
                        const int c = bn + cl;
                        float2 bs = *(const float2*)(g.bias + c);
                        *(uint32_t*)(g.outb + (size_t)rr * g.ldo + c) =
                            pk2(tanhf(v0 + bs.x), tanhf(v1 + bs.y));
                    }
                }
            }
        }
        return;
    }

    // ---- pair-exchange epilogue: lanes t,t^1 swap halves so each lane owns
    // 4 consecutive cols of one row (even->h0, odd->h1).
    const float*         bias = g.bias;
    const __nv_bfloat16* Pd   = g.Pd;
    const __nv_bfloat16* Ps   = g.Ps;
    __nv_bfloat16*       outb = g.outb;
    if (EPI == EPI_SG && isGate) {
        bias = g.bias2; Pd = g.Pd2; Ps = g.Ps2; outb = g.outb2;
    }
    const bool hi    = lane & 1;
    const int  pbase = (tig & 2) * 2;

    float colacc[4][4];
    if (EPI == EPI_MSGP) {
        #pragma unroll
        for (int ni = 0; ni < 4; ni++)
            #pragma unroll
            for (int k = 0; k < 4; k++) colacc[ni][k] = 0.f;
    }

    #pragma unroll
    for (int mi = 0; mi < 4; mi++) {
        const int rr = bm + wm + mi * 16 + gid + (hi ? 8 : 0);
        const bool val = rr < g.M;
        int di = 0, si = 0;
        if (val) { di = g.dst[rr]; si = g.srcI[rr]; }
        #pragma unroll
        for (int ni = 0; ni < 4; ni++) {
            const float x0 = acc[mi][ni][0], x1 = acc[mi][ni][1];
            const float x2 = acc[mi][ni][2], x3 = acc[mi][ni][3];
            const float r0 = __shfl_xor_sync(0xffffffffu, x0, 1);
            const float r1 = __shfl_xor_sync(0xffffffffu, x1, 1);
            const float r2 = __shfl_xor_sync(0xffffffffu, x2, 1);
            const float r3 = __shfl_xor_sync(0xffffffffu, x3, 1);
            float v[4];
            if (!hi) { v[0] = x0; v[1] = x1; v[2] = r0; v[3] = r1; }
            else     { v[0] = r2; v[1] = r3; v[2] = x2; v[3] = x3; }
            if (!val) continue;
            const int c = bn + wn + ni * 8 + pbase;
            float pd[4], ps[4], t[4];
            ub4(Pd + (size_t)di * PLD + c, pd);
            ub4(Ps + (size_t)si * PLD + c, ps);
            float4 bs = *(const float4*)(bias + c);
            t[0] = v[0] + pd[0] + ps[0] + bs.x;
            t[1] = v[1] + pd[1] + ps[1] + bs.y;
            t[2] = v[2] + pd[2] + ps[2] + bs.z;
            t[3] = v[3] + pd[3] + ps[3] + bs.w;
            if (EPI == EPI_SIGF) {
                uint2 o = make_uint2(pk2(sigm(t[0]), sigm(t[1])), pk2(sigm(t[2]), sigm(t[3])));
                *(uint2*)(outb + (size_t)rr * 768 + c) = o;
            } else if (EPI == EPI_SG) {
                if (isGate) {
                    float av[4];
                    ub4(g.aux + (size_t)rr * 768 + c, av);
                    uint2 o = make_uint2(pk2(av[0] * (1.f + sigm(t[0])), av[1] * (1.f + sigm(t[1]))),
                                         pk2(av[2] * (1.f + sigm(t[2])), av[3] * (1.f + sigm(t[3]))));
                    *(uint2*)(outb + (size_t)rr * 768 + c) = o;
                } else {
                    uint2 o = make_uint2(pk2(sigm(t[0]), sigm(t[1])), pk2(sigm(t[2]), sigm(t[3])));
                    *(uint2*)(outb + (size_t)rr * 768 + c) = o;
                }
            } else if (EPI == EPI_MSGS) {
                float av[4];
                ub4(g.aux + (size_t)rr * 768 + c, av);
                float4 m = make_float4(fmaxf(t[0], 0.f) * av[0], fmaxf(t[1], 0.f) * av[1],
                                       fmaxf(t[2], 0.f) * av[2], fmaxf(t[3], 0.f) * av[3]);
                atomicAdd((float4*)(g.atom + (size_t)di * 768 + c), m);
            } else { // EPI_MSGP: accumulate message into per-thread column sums
                float av[4];
                ub4(g.aux + (size_t)rr * 768 + c, av);
                #pragma unroll
                for (int k = 0; k < 4; k++)
                    colacc[ni][k] += fmaxf(t[k], 0.f) * av[k];
            }
        }
    }

    if (EPI == EPI_MSGP) {
        #pragma unroll
        for (int ni = 0; ni < 4; ni++) {
            #pragma unroll
            for (int k = 0; k < 4; k++) {
                float v = colacc[ni][k];
                float o;
                o = __shfl_down_sync(0xffffffffu, v, 16); if (gid < 4) v += o;
                o = __shfl_down_sync(0xffffffffu, v, 8);  if (gid < 2) v += o;
                o = __shfl_down_sync(0xffffffffu, v, 4);  if (gid < 1) v += o;
                o = __shfl_down_sync(0xffffffffu, v, 1);  if ((lane & 1) == 0) v += o;
                colacc[ni][k] = v;
            }
        }
        if (lane == 0 || lane == 2) {
            const int pb = (lane == 0) ? 0 : 4;
            #pragma unroll
            for (int ni = 0; ni < 4; ni++) {
                const int c = bn + wn + ni * 8 + pb;
                atomicAdd((float4*)(g.atom + c),
                          make_float4(colacc[ni][0], colacc[ni][1], colacc[ni][2], colacc[ni][3]));
            }
        }
    }
}

// ---------------- edge sort kernels -------------------------------------------
__global__ void hist_kernel(const int* __restrict__ dst) {
    int e = blockIdx.x * blockDim.x + threadIdx.x;
    if (e < NE) atomicAdd(&g_cnt[dst[e]], 1);
}
__global__ void scan_kernel() {   // 1 block, 1024 threads; 12 bins/thread
    __shared__ int sh[1024];
    const int t = threadIdx.x;
    const int base = t * 12;
    int loc[12];
    int sum = 0;
    #pragma unroll
    for (int i = 0; i < 12; i++) {
        int idx = base + i;
        int c = (idx < NN) ? g_cnt[idx] : 0;
        loc[i] = sum; sum += c;
    }
    sh[t] = sum;
    __syncthreads();
    for (int off = 1; off < 1024; off <<= 1) {
        int v = (t >= off) ? sh[t - off] : 0;
        __syncthreads();
        sh[t] += v;
        __syncthreads();
    }
    const int excl = (t == 0) ? 0 : sh[t - 1];
    #pragma unroll
    for (int i = 0; i < 12; i++) {
        int idx = base + i;
        if (idx < NN) g_cnt[idx] = excl + loc[i];   // cursor = exclusive base
    }
}
__global__ void scatter_kernel(const int* __restrict__ dst, const int* __restrict__ src) {
    int e = blockIdx.x * blockDim.x + threadIdx.x;
    if (e >= NE) return;
    int d = dst[e];
    int pos = atomicAdd(&g_cnt[d], 1);
    g_perm[pos] = e;
    g_dstS[pos] = d;
    g_srcS[pos] = src[e];
}

// ---------------- small kernels ----------------------------------------------
__global__ void cvt_x_kernel(const float* __restrict__ x) {
    int i = blockIdx.x * blockDim.x + threadIdx.x;
    const int n4 = NN * FF / 4;
    if (i < n4) {
        float4 v = ((const float4*)x)[i];
        ((float4*)g_x)[i] = v;
        ((__nv_bfloat162*)g_xb)[i * 2]     = __floats2bfloat162_rn(v.x, v.y);
        ((__nv_bfloat162*)g_xb)[i * 2 + 1] = __floats2bfloat162_rn(v.z, v.w);
    }
    if (i < FF) { g_pool[i] = 0.f; g_poolE[i] = 0.f; }
    if (i < NN) g_cnt[i] = 0;
}
__global__ void cvt_bf16_kernel(const float* __restrict__ s, __nv_bfloat16* __restrict__ d, int n4) {
    int i = blockIdx.x * blockDim.x + threadIdx.x;
    if (i < n4) {
        float4 v = ((const float4*)s)[i];
        ((__nv_bfloat162*)d)[i * 2]     = __floats2bfloat162_rn(v.x, v.y);
        ((__nv_bfloat162*)d)[i * 2 + 1] = __floats2bfloat162_rn(v.z, v.w);
    }
}
// x1 refresh fused with GlobalSumPool: convert g_x -> g_xb AND accumulate
// column sums into g_pool. 300 blocks x 192 threads; block = 40 rows.
__global__ void cvt_pool_kernel() {
    const int c  = threadIdx.x * 4;          // column (0..764)
    const int r0 = blockIdx.x * 40;
    float s0 = 0.f, s1 = 0.f, s2 = 0.f, s3 = 0.f;
    for (int r = r0; r < r0 + 40; r++) {
        float4 v = *(const float4*)(g_x + (size_t)r * FF + c);
        ((__nv_bfloat162*)(g_xb + (size_t)r * FF + c))[0] = __floats2bfloat162_rn(v.x, v.y);
        ((__nv_bfloat162*)(g_xb + (size_t)r * FF + c))[1] = __floats2bfloat162_rn(v.z, v.w);
        s0 += v.x; s1 += v.y; s2 += v.z; s3 += v.w;
    }
    atomicAdd((float4*)(g_pool + c), make_float4(s0, s1, s2, s3));
}
__global__ void final_kernel(const float* __restrict__ Wd, const float* __restrict__ bd,
                             float* __restrict__ out) {
    int l = threadIdx.x;
    float logit = -1e30f;
    if (l < 16) {
        float s = bd[l];
        #pragma unroll 8
        for (int f = 0; f < FF; f++) s += (g_pool[f] + g_poolE[f]) * Wd[f * 16 + l];
        logit = s;
    }
    float m = logit;
    #pragma unroll
    for (int o = 16; o > 0; o >>= 1) m = fmaxf(m, __shfl_xor_sync(0xffffffffu, m, o));
    float e = (l < 16) ? __expf(logit - m) : 0.f;
    float sum = e;
    #pragma unroll
    for (int o = 16; o > 0; o >>= 1) sum += __shfl_xor_sync(0xffffffffu, sum, o);
    if (l < 16) out[l] = e / sum;
}

// ---------------- host orchestration ------------------------------------------
extern "C" void kernel_launch(void* const* d_in, const int* in_sizes, int n_in,
                              void* d_out, int out_size) {
    (void)in_sizes; (void)n_in; (void)out_size;
    const float* x     = (const float*)d_in[0];
    const float* e_raw = (const float*)d_in[1];
    const int*   src   = (const int*)d_in[2];
    const int*   dst   = (const int*)d_in[3];
    const float* W_pre = (const float*)d_in[4];
    const float* b_pre = (const float*)d_in[5];
    const float* Wf1 = (const float*)d_in[6],  *bf1 = (const float*)d_in[7];
    const float* Ws1 = (const float*)d_in[8],  *bs1 = (const float*)d_in[9];
    const float* We1 = (const float*)d_in[10], *be1 = (const float*)d_in[11];
    const float* Wf2 = (const float*)d_in[12], *bf2 = (const float*)d_in[13];
    const float* Ws2 = (const float*)d_in[14], *bs2 = (const float*)d_in[15];
    const float* Wd  = (const float*)d_in[18], *bd  = (const float*)d_in[19];

    void *pe1v, *pe2v, *pSfv, *pPv, *pxv, *pxbv, *perbv, *pWtv, *ppermv, *pdstSv, *psrcSv, *ppoolEv;
    cudaGetSymbolAddress(&pe1v,   g_e1);
    cudaGetSymbolAddress(&pe2v,   g_e2);
    cudaGetSymbolAddress(&pSfv,   g_Sf);
    cudaGetSymbolAddress(&pPv,    g_P);
    cudaGetSymbolAddress(&pxv,    g_x);
    cudaGetSymbolAddress(&pxbv,   g_xb);
    cudaGetSymbolAddress(&perbv,  g_erb);
    cudaGetSymbolAddress(&pWtv,   g_Wt);
    cudaGetSymbolAddress(&ppermv, g_perm);
    cudaGetSymbolAddress(&pdstSv, g_dstS);
    cudaGetSymbolAddress(&psrcSv, g_srcS);
    cudaGetSymbolAddress(&ppoolEv, g_poolE);
    __nv_bfloat16* pe1   = (__nv_bfloat16*)pe1v;
    __nv_bfloat16* pe2   = (__nv_bfloat16*)pe2v;
    __nv_bfloat16* pSf   = (__nv_bfloat16*)pSfv;
    __nv_bfloat16* pP    = (__nv_bfloat16*)pPv;
    float*         px    = (float*)pxv;
    __nv_bfloat16* pxb   = (__nv_bfloat16*)pxbv;
    __nv_bfloat16* perb  = (__nv_bfloat16*)perbv;
    __nv_bfloat16* pWt   = (__nv_bfloat16*)pWtv;
    const int*     pperm = (const int*)ppermv;
    const int*     pdstS = (const int*)pdstSv;
    const int*     psrcS = (const int*)psrcSv;
    float*         ppoolE = (float*)ppoolEv;

    cudaFuncSetAttribute(gemm_k<EPI_STORE>, cudaFuncAttributeMaxDynamicSharedMemorySize, SMEM_BYTES);
    cudaFuncSetAttribute(gemm_k<EPI_TANH>,  cudaFuncAttributeMaxDynamicSharedMemorySize, SMEM_BYTES);
    cudaFuncSetAttribute(gemm_k<EPI_SIGF>,  cudaFuncAttributeMaxDynamicSharedMemorySize, SMEM_BYTES);
    cudaFuncSetAttribute(gemm_k<EPI_MSGS>,  cudaFuncAttributeMaxDynamicSharedMemorySize, SMEM_BYTES);
    cudaFuncSetAttribute(gemm_k<EPI_SG>,    cudaFuncAttributeMaxDynamicSharedMemorySize, SMEM_BYTES);
    cudaFuncSetAttribute(gemm_k<EPI_MSGP>,  cudaFuncAttributeMaxDynamicSharedMemorySize, SMEM_BYTES);

    const dim3 blk(256);
    const dim3 gE(6,  (NE + 127) / 128);
    const dim3 gSG(12, (NE + 127) / 128);
    const dim3 gN1(36, (NN + 127) / 128);
    const dim3 gN2(24, (NN + 127) / 128);
    auto slot = [&](int i) { return pWt + (size_t)i * SLOT; };

    // (1) x -> g_x + g_xb, zero pools + g_cnt   (2) e_raw -> bf16   (3) weights
    cvt_x_kernel<<<(NN * FF / 4 + 255) / 256, blk>>>(x);
    cvt_bf16_kernel<<<(NE * 64 / 4 + 255) / 256, blk>>>(e_raw, perb, NE * 64 / 4);
    {
        // all 16 weight slots, one launch
        const int big = (int)(3 * SLOT / 4);
        const int tot4 = 5 * big + 64 * FF / 4;
        // reuse cvt_bf16 via a combined kernel below (cvt_w)
        extern __global__ void cvt_w_kernel(const float*, const float*, const float*,
                                            const float*, const float*, const float*);
        cvt_w_kernel<<<(tot4 + 255) / 256, blk>>>(Wf1, Ws1, We1, Wf2, Ws2, W_pre);
    }

    auto node_pass = [&](int slotBase, dim3 grid) {
        GArgs a = {};
        a.A = pxb; a.lda = 768; a.M = NN; a.K = 768;
        a.B = pWt; a.ldb = 768;
        a.outb = pP; a.ldo = PLD;
        a.multi = 1; a.slotBase = slotBase;
        gemm_k<EPI_STORE><<<grid, blk, SMEM_BYTES>>>(a);
    };

    // (4) conv1 node projections  [ncu capture target]
    node_pass(0, gN1);

    // (5-7) edge counting-sort by dst: hist -> scan -> scatter (cnt zeroed in (1))
    hist_kernel<<<(NE + 255) / 256, blk>>>(dst);
    scan_kernel<<<1, 1024>>>();
    scatter_kernel<<<(NE + 255) / 256, blk>>>(dst, src);

    // (8) pre-edge: e1[sorted] = tanh(e_raw[perm] @ W_pre + b_pre)
    {
        GArgs a = {};
        a.A = perb; a.lda = 64; a.M = NE; a.K = 64;
        a.B = slot(15); a.ldb = 768; a.bias = b_pre;
        a.outb = pe1; a.ldo = 768;
        a.permA = pperm;
        gemm_k<EPI_TANH><<<gE, blk, SMEM_BYTES>>>(a);
    }

    // (9) conv1 merged SIGF+GATE
    {
        GArgs a = {};
        a.A = pe1; a.lda = 768; a.M = NE; a.K = 768;
        a.B = slot(2); a.B2 = slot(8); a.ldb = 768;
        a.bias = bf1; a.bias2 = be1;
        a.Pd = pP + 0;     a.Ps = pP + 768;
        a.Pd2 = pP + 3072; a.Ps2 = pP + 3840;
        a.dst = pdstS; a.srcI = psrcS;
        a.aux = pe1; a.outb = pSf; a.outb2 = pe2; a.ldo = 768;
        gemm_k<EPI_SG><<<gSG, blk, SMEM_BYTES>>>(a);
    }

    // (10) conv1 MSGS: x += scatter(relu(s-head) * Sf)
    {
        GArgs a = {};
        a.A = pe1; a.lda = 768; a.M = NE; a.K = 768;
        a.B = slot(5); a.ldb = 768; a.bias = bs1;
        a.Pd = pP + 1536; a.Ps = pP + 2304;
        a.dst = pdstS; a.srcI = psrcS;
        a.aux = pSf; a.ldo = 768; a.atom = px;
        gemm_k<EPI_MSGS><<<gE, blk, SMEM_BYTES>>>(a);
    }

    // (11) refresh bf16 node features + pool(x1) in one pass
    cvt_pool_kernel<<<300, 192>>>();

    // (12) conv2 node projections
    node_pass(9, gN2);

    // (13) conv2 SIGF
    {
        GArgs a = {};
        a.A = pe2; a.lda = 768; a.M = NE; a.K = 768;
        a.B = slot(11); a.ldb = 768; a.bias = bf2;
        a.Pd = pP + 0; a.Ps = pP + 768;
        a.dst = pdstS; a.srcI = psrcS;
        a.outb = pSf; a.ldo = 768;
        gemm_k<EPI_SIGF><<<gE, blk, SMEM_BYTES>>>(a);
    }
    // (14) conv2 MSGP: poolE += sum over edges of relu(s)*Sf
    {
        GArgs a = {};
        a.A = pe2; a.lda = 768; a.M = NE; a.K = 768;
        a.B = slot(14); a.ldb = 768; a.bias = bs2;
        a.Pd = pP + 1536; a.Ps = pP + 2304;
        a.dst = pdstS; a.srcI = psrcS;
        a.aux = pSf; a.ldo = 768; a.atom = ppoolE;
        gemm_k<EPI_MSGP><<<gE, blk, SMEM_BYTES>>>(a);
    }

    // (15) dense + softmax
    final_kernel<<<1, 32>>>(Wd, bd, (float*)d_out);
}

// weight conversion (all 16 slots, one launch)
__global__ void cvt_w_kernel(const float* Wf1, const float* Ws1, const float* We1,
                             const float* Wf2, const float* Ws2, const float* Wp) {
    int i = blockIdx.x * blockDim.x + threadIdx.x;    // float4 index
    const int big = (int)(3 * SLOT / 4);
    const float* s;
    __nv_bfloat16* d;
    if (i < 5 * big) {
        int w = i / big, r = i - w * big;
        const float* sv = Wf1;
        if (w == 1) sv = Ws1; else if (w == 2) sv = We1;
        else if (w == 3) sv = Wf2; else if (w == 4) sv = Ws2;
        s = sv + (size_t)r * 4;
        d = g_Wt + (size_t)w * 3 * SLOT + (size_t)r * 4;
    } else {
        int r = i - 5 * big;
        if (r >= 64 * FF / 4) return;
        s = Wp + (size_t)r * 4;
        d = g_Wt + (size_t)15 * SLOT + (size_t)r * 4;
    }
    float4 v = *(const float4*)s;
    *(__nv_bfloat162*)d       = __floats2bfloat162_rn(v.x, v.y);
    *(__nv_bfloat162*)(d + 2) = __floats2bfloat162_rn(v.z, v.w);
}